// round 14
// baseline (speedup 1.0000x reference)
#include <cuda_runtime.h>
#include <cuda_fp16.h>
#include <math.h>

#define Nn   100000
#define Ee   1600000
#define FIN  128
#define HH   64
#define GG   256
#define NEG_INF __int_as_float(0xff800000)

typedef unsigned long long u64;

// ---------------- f32x2 helpers (PTX-only; ptxas never auto-fuses) ----------------
__device__ __forceinline__ u64 pack2(float lo, float hi) {
    u64 r; asm("mov.b64 %0, {%1, %2};" : "=l"(r) : "f"(lo), "f"(hi)); return r;
}
__device__ __forceinline__ void fma2(u64& d, u64 a, u64 b) {
    asm("fma.rn.f32x2 %0, %1, %2, %0;" : "+l"(d) : "l"(a), "l"(b));
}
__device__ __forceinline__ float2 unpack2(u64 v) {
    float2 f; asm("mov.b64 {%0, %1}, %2;" : "=f"(f.x), "=f"(f.y) : "l"(v)); return f;
}

__device__ __forceinline__ __half2 u2h(unsigned u) { return *reinterpret_cast<__half2*>(&u); }
__device__ __forceinline__ unsigned h2u(__half2 h) { return *reinterpret_cast<unsigned*>(&h); }
#define H2_NEGINF 0xFC00FC00u
__device__ __forceinline__ unsigned umax_h2(unsigned a, unsigned b) {
    return h2u(__hmax2(u2h(a), u2h(b)));
}

// ---------------- device scratch ----------------
__device__ int     g_deg[Nn];
__device__ int     g_rowptr[Nn];
__device__ int     g_fill[Nn];
__device__ int     g_csr[Ee];
__device__ int     g_bsum[128];
__device__ __half2 g_xh[(size_t)Nn * 64];    // fp16 copy of x (128 feats)
__device__ __half2 g_agg[(size_t)Nn * 64];   // fp16 agg (128 feats L1 / 64 feats L2,L3)
__device__ __half2 g_h1[(size_t)Nn * 32];
__device__ __half2 g_h2[(size_t)Nn * 32];
__device__ float   g_h3[(size_t)Nn * HH];
__device__ float   g_c[Nn];
__device__ float   g_e[Nn];

// ---------------- CSR build ----------------
__global__ void hist_kernel(const int* __restrict__ ei) {
    int e = blockIdx.x * blockDim.x + threadIdx.x;
    if (e < Ee) atomicAdd(&g_deg[__ldg(&ei[Ee + e])], 1);
}

__global__ void scan_a_kernel() {
    __shared__ int wsum[32];
    int tid = threadIdx.x;
    int i = blockIdx.x * 1024 + tid;
    int v = (i < Nn) ? g_deg[i] : 0;
    int lane = tid & 31, wid = tid >> 5;
    int x = v;
#pragma unroll
    for (int o = 1; o < 32; o <<= 1) {
        int y = __shfl_up_sync(0xffffffffu, x, o);
        if (lane >= o) x += y;
    }
    if (lane == 31) wsum[wid] = x;
    __syncthreads();
    if (wid == 0) {
        int w = wsum[lane];
        int xx = w;
#pragma unroll
        for (int o = 1; o < 32; o <<= 1) {
            int y = __shfl_up_sync(0xffffffffu, xx, o);
            if (lane >= o) xx += y;
        }
        wsum[lane] = xx - w;
    }
    __syncthreads();
    int excl = x - v + wsum[wid];
    if (i < Nn) g_rowptr[i] = excl;
    if (tid == 1023) g_bsum[blockIdx.x] = excl + v;
}

__global__ void scan_c_kernel(int nb) {
    __shared__ int ws[4];
    __shared__ int soff;
    int tid = threadIdx.x;
    if (tid < 128) {
        int v = (tid < nb && tid < blockIdx.x) ? g_bsum[tid] : 0;
#pragma unroll
        for (int o = 16; o > 0; o >>= 1) v += __shfl_down_sync(0xffffffffu, v, o);
        if ((tid & 31) == 0) ws[tid >> 5] = v;
    }
    __syncthreads();
    if (tid == 0) soff = ws[0] + ws[1] + ws[2] + ws[3];
    __syncthreads();
    int i = blockIdx.x * 1024 + tid;
    if (i < Nn) {
        int r = g_rowptr[i] + soff;
        g_rowptr[i] = r;
        g_fill[i] = r;
    }
}

__global__ void csr_scatter_kernel(const int* __restrict__ ei) {
    int e = blockIdx.x * blockDim.x + threadIdx.x;
    if (e >= Ee) return;
    int src = __ldg(&ei[e]);
    int dst = __ldg(&ei[Ee + e]);
    int pos = atomicAdd(&g_fill[dst], 1);
    g_csr[pos] = src;
}

// ---------------- x -> fp16 conversion (+ zero g_deg, folded) ----------------
__global__ void convert_x_kernel(const float4* __restrict__ x4, uint2* __restrict__ xh) {
    int i = blockIdx.x * blockDim.x + threadIdx.x;   // Nn*32 float4s
    if (i < Nn) g_deg[i] = 0;
    if (i >= Nn * 32) return;
    float4 v = __ldg(&x4[i]);
    uint2 o;
    o.x = h2u(__floats2half2_rn(v.x, v.y));
    o.y = h2u(__floats2half2_rn(v.z, v.w));
    xh[i] = o;
}

// ---------------- segmented max (gather, fp16 rows) ----------------
// Layer 1: one warp per node, uint2 per lane (4 fp16 feats; row = 256 B). MLP=16.
__global__ void agg_max128_h(const uint2* __restrict__ xh, uint2* __restrict__ aggh) {
    int t = blockIdx.x * blockDim.x + threadIdx.x;
    int w = t >> 5;
    if (w >= Nn) return;
    int lane = t & 31;
    int start = g_rowptr[w];
    int d = g_deg[w];
    unsigned m0 = H2_NEGINF, m1 = H2_NEGINF;
    int i = 0;
    for (; i + 16 <= d; i += 16) {
        int idx[16];
#pragma unroll
        for (int j = 0; j < 16; j++) idx[j] = g_csr[start + i + j];
        uint2 v[16];
#pragma unroll
        for (int j = 0; j < 16; j++) v[j] = __ldg(&xh[(size_t)idx[j] * 32 + lane]);
#pragma unroll
        for (int j = 0; j < 16; j++) { m0 = umax_h2(m0, v[j].x); m1 = umax_h2(m1, v[j].y); }
    }
    if (i + 8 <= d) {
        int idx[8];
#pragma unroll
        for (int j = 0; j < 8; j++) idx[j] = g_csr[start + i + j];
        uint2 v[8];
#pragma unroll
        for (int j = 0; j < 8; j++) v[j] = __ldg(&xh[(size_t)idx[j] * 32 + lane]);
#pragma unroll
        for (int j = 0; j < 8; j++) { m0 = umax_h2(m0, v[j].x); m1 = umax_h2(m1, v[j].y); }
        i += 8;
    }
    if (i + 4 <= d) {
        int idx[4];
#pragma unroll
        for (int j = 0; j < 4; j++) idx[j] = g_csr[start + i + j];
        uint2 v[4];
#pragma unroll
        for (int j = 0; j < 4; j++) v[j] = __ldg(&xh[(size_t)idx[j] * 32 + lane]);
#pragma unroll
        for (int j = 0; j < 4; j++) { m0 = umax_h2(m0, v[j].x); m1 = umax_h2(m1, v[j].y); }
        i += 4;
    }
    for (; i < d; i++) {
        uint2 v = __ldg(&xh[(size_t)g_csr[start + i] * 32 + lane]);
        m0 = umax_h2(m0, v.x); m1 = umax_h2(m1, v.y);
    }
    if (d == 0) { m0 = 0u; m1 = 0u; }
    uint2 o; o.x = m0; o.y = m1;
    aggh[(size_t)w * 32 + lane] = o;
}

// Layers 2/3: one warp per node, one half2 per lane (64 fp16 feats). MLP=16.
__global__ void agg_max64_h(const __half2* __restrict__ hsrc, __half2* __restrict__ aggh) {
    int t = blockIdx.x * blockDim.x + threadIdx.x;
    int w = t >> 5;
    if (w >= Nn) return;
    int lane = t & 31;
    int start = g_rowptr[w];
    int d = g_deg[w];
    unsigned m = H2_NEGINF;
    int i = 0;
    for (; i + 16 <= d; i += 16) {
        int idx[16];
#pragma unroll
        for (int j = 0; j < 16; j++) idx[j] = g_csr[start + i + j];
        unsigned v[16];
#pragma unroll
        for (int j = 0; j < 16; j++) v[j] = h2u(__ldg(&hsrc[(size_t)idx[j] * 32 + lane]));
#pragma unroll
        for (int j = 0; j < 16; j++) m = umax_h2(m, v[j]);
    }
    if (i + 8 <= d) {
        int idx[8];
#pragma unroll
        for (int j = 0; j < 8; j++) idx[j] = g_csr[start + i + j];
        unsigned v[8];
#pragma unroll
        for (int j = 0; j < 8; j++) v[j] = h2u(__ldg(&hsrc[(size_t)idx[j] * 32 + lane]));
#pragma unroll
        for (int j = 0; j < 8; j++) m = umax_h2(m, v[j]);
        i += 8;
    }
    if (i + 4 <= d) {
        int idx[4];
#pragma unroll
        for (int j = 0; j < 4; j++) idx[j] = g_csr[start + i + j];
        unsigned v[4];
#pragma unroll
        for (int j = 0; j < 4; j++) v[j] = h2u(__ldg(&hsrc[(size_t)idx[j] * 32 + lane]));
#pragma unroll
        for (int j = 0; j < 4; j++) m = umax_h2(m, v[j]);
        i += 4;
    }
    for (; i < d; i++)
        m = umax_h2(m, h2u(__ldg(&hsrc[(size_t)g_csr[start + i] * 32 + lane])));
    if (d == 0) m = 0u;
    aggh[(size_t)w * 32 + lane] = u2h(m);
}

// ---------------- fused SAGE layer GEMM (f32x2, 2 nodes x 8 feats per thread) ----
// Block: 256 threads, tile 64 nodes x 64 out-feats, static smem (occupancy as R12).
// tx = tid&7 (8 feat-groups of 8), ty = tid>>3 (32 node-groups); nodes ty, ty+32.
// Per-output accumulation order identical to R12 (bit-exact).
template <int K, bool OH>
__global__ void __launch_bounds__(256)
sage_gemm(const __half2* __restrict__ agg_h, const __half2* __restrict__ xin_h,
          const float* __restrict__ Wl, const float* __restrict__ blv,
          const float* __restrict__ Wr, void* __restrict__ out_v) {
    __shared__ float sA[64][68];
    __shared__ float sX[64][68];

    const int tid = threadIdx.x;
    const int tx = tid & 7;
    const int ty = tid >> 3;
    const int node0 = blockIdx.x * 64;

    u64 acc[2][4];
#pragma unroll
    for (int i = 0; i < 2; i++)
#pragma unroll
        for (int j = 0; j < 4; j++) acc[i][j] = 0ULL;

    for (int k0 = 0; k0 < K; k0 += 64) {
        __syncthreads();
#pragma unroll
        for (int t = tid; t < 64 * 16; t += 256) {
            int nn = t >> 4;
            int ck = t & 15;
            int node = node0 + nn;
            float4 a = make_float4(0.f, 0.f, 0.f, 0.f);
            float4 xv = a;
            if (node < Nn) {
                size_t off = (size_t)node * (K / 2) + (k0 >> 1) + ck * 2;
                uint2 ra = *(const uint2*)&agg_h[off];
                float2 alo = __half22float2(u2h(ra.x));
                float2 ahi = __half22float2(u2h(ra.y));
                a = make_float4(alo.x, alo.y, ahi.x, ahi.y);
                uint2 rx = *(const uint2*)&xin_h[off];
                float2 xlo = __half22float2(u2h(rx.x));
                float2 xhi = __half22float2(u2h(rx.y));
                xv = make_float4(xlo.x, xlo.y, xhi.x, xhi.y);
            }
            *(float4*)&sA[nn][ck * 4] = a;
            *(float4*)&sX[nn][ck * 4] = xv;
        }
        __syncthreads();

#pragma unroll 8
        for (int kk = 0; kk < 64; kk++) {
            const float* wrow_l = &Wl[(size_t)(k0 + kk) * 64 + tx * 8];
            const float* wrow_r = &Wr[(size_t)(k0 + kk) * 64 + tx * 8];
            const ulonglong2 wlA = *(const ulonglong2*)wrow_l;
            const ulonglong2 wlB = *(const ulonglong2*)(wrow_l + 4);
            const ulonglong2 wrA = *(const ulonglong2*)wrow_r;
            const ulonglong2 wrB = *(const ulonglong2*)(wrow_r + 4);
#pragma unroll
            for (int i = 0; i < 2; i++) {
                int nn = ty + 32 * i;
                float a  = sA[nn][kk];
                float xv = sX[nn][kk];
                u64 a2 = pack2(a, a);
                u64 x2 = pack2(xv, xv);
                fma2(acc[i][0], a2, wlA.x);
                fma2(acc[i][1], a2, wlA.y);
                fma2(acc[i][2], a2, wlB.x);
                fma2(acc[i][3], a2, wlB.y);
                fma2(acc[i][0], x2, wrA.x);
                fma2(acc[i][1], x2, wrA.y);
                fma2(acc[i][2], x2, wrB.x);
                fma2(acc[i][3], x2, wrB.y);
            }
        }
    }

    const float4 bA = *(const float4*)&blv[tx * 8];
    const float4 bB = *(const float4*)&blv[tx * 8 + 4];
#pragma unroll
    for (int i = 0; i < 2; i++) {
        int node = node0 + ty + 32 * i;
        if (node < Nn) {
            float2 p0 = unpack2(acc[i][0]);
            float2 p1 = unpack2(acc[i][1]);
            float2 p2 = unpack2(acc[i][2]);
            float2 p3 = unpack2(acc[i][3]);
            float o0 = fmaxf(p0.x + bA.x, 0.f);
            float o1 = fmaxf(p0.y + bA.y, 0.f);
            float o2 = fmaxf(p1.x + bA.z, 0.f);
            float o3 = fmaxf(p1.y + bA.w, 0.f);
            float o4 = fmaxf(p2.x + bB.x, 0.f);
            float o5 = fmaxf(p2.y + bB.y, 0.f);
            float o6 = fmaxf(p3.x + bB.z, 0.f);
            float o7 = fmaxf(p3.y + bB.w, 0.f);
            if (OH) {
                __half2* oh = (__half2*)out_v;
                uint4 w4;
                w4.x = h2u(__floats2half2_rn(o0, o1));
                w4.y = h2u(__floats2half2_rn(o2, o3));
                w4.z = h2u(__floats2half2_rn(o4, o5));
                w4.w = h2u(__floats2half2_rn(o6, o7));
                *(uint4*)&oh[(size_t)node * 32 + tx * 4] = w4;
            } else {
                float* of = (float*)out_v;
                *(float4*)&of[(size_t)node * 64 + tx * 8]     = make_float4(o0, o1, o2, o3);
                *(float4*)&of[(size_t)node * 64 + tx * 8 + 4] = make_float4(o4, o5, o6, o7);
            }
        }
    }
}

// ---------------- fused attention pooling: one block per graph ----------------
__global__ void __launch_bounds__(256)
fused_pool_kernel(const float4* __restrict__ clo4, const float* __restrict__ Wc,
                  const float* __restrict__ bc, const int* __restrict__ batch,
                  const float* __restrict__ h3,
                  const float* __restrict__ Wa1, const float* __restrict__ ba1,
                  const float* __restrict__ Wa2, const float* __restrict__ ba2,
                  float* __restrict__ out) {
    const int g = blockIdx.x;
    const int tid = threadIdx.x;
    const int lane = tid & 31, wid = tid >> 5;

    __shared__ int sS, sE;
    __shared__ float red[32];
    __shared__ float s_bcast;
    __shared__ float pooled[64];

    if (tid == 0) {
        int lo = 0, hi = Nn;
        while (lo < hi) { int mid = (lo + hi) >> 1; if (batch[mid] < g) lo = mid + 1; else hi = mid; }
        sS = lo;
        hi = Nn;
        while (lo < hi) { int mid = (lo + hi) >> 1; if (batch[mid] < g + 1) lo = mid + 1; else hi = mid; }
        sE = lo;
    }
    __syncthreads();
    const int s = sS, e = sE;
    const int count = e - s;

    float wc[16];
#pragma unroll
    for (int q = 0; q < 16; q++) wc[q] = Wc[q];
    float bias = bc[0];

    float lmax = NEG_INF;
    for (int i = s + tid; i < e; i += 256) {
        float cv = bias;
#pragma unroll
        for (int q = 0; q < 4; q++) {
            float4 c4 = __ldg(&clo4[(size_t)i * 4 + q]);
            cv += c4.x * wc[q * 4 + 0] + c4.y * wc[q * 4 + 1] + c4.z * wc[q * 4 + 2] + c4.w * wc[q * 4 + 3];
        }
        g_c[i] = cv;
        lmax = fmaxf(lmax, cv);
    }
#pragma unroll
    for (int o = 16; o > 0; o >>= 1) lmax = fmaxf(lmax, __shfl_xor_sync(0xffffffffu, lmax, o));
    if (lane == 0) red[wid] = lmax;
    __syncthreads();
    if (tid == 0) {
        float m = red[0];
#pragma unroll
        for (int q = 1; q < 8; q++) m = fmaxf(m, red[q]);
        s_bcast = m;
    }
    __syncthreads();
    const float cmax = s_bcast;

    float lsum = 0.f;
    for (int i = s + tid; i < e; i += 256) {
        float ev = expf(g_c[i] - cmax);
        g_e[i] = ev;
        lsum += ev;
    }
#pragma unroll
    for (int o = 16; o > 0; o >>= 1) lsum += __shfl_xor_sync(0xffffffffu, lsum, o);
    if (lane == 0) red[wid] = lsum;
    __syncthreads();
    if (tid == 0) {
        float m = 0.f;
#pragma unroll
        for (int q = 0; q < 8; q++) m += red[q];
        s_bcast = m;
    }
    __syncthreads();
    const float denom = s_bcast;
    const float scale = (count > 0) ? ((float)count / denom) : 0.f;

    const int f = tid & 63;
    const int grp = tid >> 6;
    float lm = NEG_INF;
    for (int i = s + grp; i < e; i += 4) {
        float p = g_e[i] * scale;
        lm = fmaxf(lm, p * __ldg(&h3[(size_t)i * 64 + f]));
    }
    __syncthreads();
    __shared__ float pgrp[4][64];
    pgrp[grp][f] = lm;
    __syncthreads();
    if (tid < 64) {
        float m = fmaxf(fmaxf(pgrp[0][tid], pgrp[1][tid]), fmaxf(pgrp[2][tid], pgrp[3][tid]));
        pooled[tid] = (count > 0) ? m : 0.f;
    }
    __syncthreads();

    if (tid < 16) {
        float sj = ba1[tid];
        for (int ff = 0; ff < 64; ff++) sj += pooled[ff] * Wa1[ff * 16 + tid];
        sj = fmaxf(sj, 0.f) * Wa2[tid];
#pragma unroll
        for (int o = 8; o > 0; o >>= 1) sj += __shfl_down_sync(0x0000ffffu, sj, o, 16);
        if (tid == 0) out[g] = sj + ba2[0];
    }
}

// ---------------- launch ----------------
extern "C" void kernel_launch(void* const* d_in, const int* in_sizes, int n_in,
                              void* d_out, int out_size) {
    const float* x     = (const float*)d_in[0];
    const int*   ei    = (const int*)d_in[1];
    const int*   batch = (const int*)d_in[2];
    const float* clo   = (const float*)d_in[3];
    const float* W1l = (const float*)d_in[4];
    const float* b1l = (const float*)d_in[5];
    const float* W1r = (const float*)d_in[6];
    const float* W2l = (const float*)d_in[7];
    const float* b2l = (const float*)d_in[8];
    const float* W2r = (const float*)d_in[9];
    const float* W3l = (const float*)d_in[10];
    const float* b3l = (const float*)d_in[11];
    const float* W3r = (const float*)d_in[12];
    const float* Wc  = (const float*)d_in[13];
    const float* bc  = (const float*)d_in[14];
    const float* Wa1 = (const float*)d_in[15];
    const float* ba1 = (const float*)d_in[16];
    const float* Wa2 = (const float*)d_in[17];
    const float* ba2 = (const float*)d_in[18];
    float* out = (float*)d_out;

    __half2* xh;  cudaGetSymbolAddress((void**)&xh, g_xh);
    __half2* agg; cudaGetSymbolAddress((void**)&agg, g_agg);
    __half2* h1;  cudaGetSymbolAddress((void**)&h1, g_h1);
    __half2* h2;  cudaGetSymbolAddress((void**)&h2, g_h2);
    float*   h3;  cudaGetSymbolAddress((void**)&h3, g_h3);

    const int TB = 256;
    const int SCAN_BLOCKS = (Nn + 1023) / 1024;  // 98
    const int GBLK = (Nn + 63) / 64;             // 1563

    // ---- x conversion (also zeroes g_deg) + CSR build (by dst) ----
    convert_x_kernel<<<(Nn * 32 + TB - 1) / TB, TB>>>((const float4*)x, (uint2*)xh);
    hist_kernel<<<(Ee + TB - 1) / TB, TB>>>(ei);
    scan_a_kernel<<<SCAN_BLOCKS, 1024>>>();
    scan_c_kernel<<<SCAN_BLOCKS, 1024>>>(SCAN_BLOCKS);
    csr_scatter_kernel<<<(Ee + TB - 1) / TB, TB>>>(ei);

    // ---- layer 1 (K = 128, fp16 agg+x, fp16 out) ----
    agg_max128_h<<<(Nn * 32 + TB - 1) / TB, TB>>>((const uint2*)xh, (uint2*)agg);
    sage_gemm<128, true><<<GBLK, TB>>>(agg, xh, W1l, b1l, W1r, h1);

    // ---- layer 2 (K = 64, fp16 agg+x, fp16 out) ----
    agg_max64_h<<<(Nn * 32 + TB - 1) / TB, TB>>>(h1, agg);
    sage_gemm<64, true><<<GBLK, TB>>>(agg, h1, W2l, b2l, W2r, h2);

    // ---- layer 3 (K = 64, fp16 agg+x, fp32 out) ----
    agg_max64_h<<<(Nn * 32 + TB - 1) / TB, TB>>>(h2, agg);
    sage_gemm<64, false><<<GBLK, TB>>>(agg, h2, W3l, b3l, W3r, h3);

    // ---- fused attention pooling + readout ----
    fused_pool_kernel<<<GG, 256>>>((const float4*)clo, Wc, bc, batch, h3,
                                   Wa1, ba1, Wa2, ba2, out);
}

// round 15
// speedup vs baseline: 1.5203x; 1.5203x over previous
#include <cuda_runtime.h>
#include <cuda_fp16.h>
#include <math.h>

#define Nn   100000
#define Ee   1600000
#define FIN  128
#define HH   64
#define GG   256
#define NEG_INF __int_as_float(0xff800000)

typedef unsigned long long u64;

// ---------------- f32x2 helpers (PTX-only; ptxas never auto-fuses) ----------------
__device__ __forceinline__ u64 pack2(float lo, float hi) {
    u64 r; asm("mov.b64 %0, {%1, %2};" : "=l"(r) : "f"(lo), "f"(hi)); return r;
}
__device__ __forceinline__ void fma2(u64& d, u64 a, u64 b) {
    asm("fma.rn.f32x2 %0, %1, %2, %0;" : "+l"(d) : "l"(a), "l"(b));
}
__device__ __forceinline__ float2 unpack2(u64 v) {
    float2 f; asm("mov.b64 {%0, %1}, %2;" : "=f"(f.x), "=f"(f.y) : "l"(v)); return f;
}

__device__ __forceinline__ __half2 u2h(unsigned u) { return *reinterpret_cast<__half2*>(&u); }
__device__ __forceinline__ unsigned h2u(__half2 h) { return *reinterpret_cast<unsigned*>(&h); }
#define H2_NEGINF 0xFC00FC00u
__device__ __forceinline__ unsigned umax_h2(unsigned a, unsigned b) {
    return h2u(__hmax2(u2h(a), u2h(b)));
}

// ---------------- device scratch ----------------
__device__ int     g_deg[Nn];
__device__ int     g_rowptr[Nn];
__device__ int     g_fill[Nn];
__device__ int     g_csr[Ee];
__device__ int     g_bsum[128];
__device__ __half2 g_xh[(size_t)Nn * 64];    // fp16 copy of x (128 feats)
__device__ __half2 g_agg[(size_t)Nn * 64];   // fp16 agg (128 feats L1 / 64 feats L2,L3)
__device__ __half2 g_h1[(size_t)Nn * 32];
__device__ __half2 g_h2[(size_t)Nn * 32];
__device__ float   g_h3[(size_t)Nn * HH];
__device__ float   g_c[Nn];
__device__ float   g_e[Nn];

// ---------------- CSR build ----------------
__global__ void hist_kernel(const int* __restrict__ ei) {
    int e = blockIdx.x * blockDim.x + threadIdx.x;
    if (e < Ee) atomicAdd(&g_deg[__ldg(&ei[Ee + e])], 1);
}

__global__ void scan_a_kernel() {
    __shared__ int wsum[32];
    int tid = threadIdx.x;
    int i = blockIdx.x * 1024 + tid;
    int v = (i < Nn) ? g_deg[i] : 0;
    int lane = tid & 31, wid = tid >> 5;
    int x = v;
#pragma unroll
    for (int o = 1; o < 32; o <<= 1) {
        int y = __shfl_up_sync(0xffffffffu, x, o);
        if (lane >= o) x += y;
    }
    if (lane == 31) wsum[wid] = x;
    __syncthreads();
    if (wid == 0) {
        int w = wsum[lane];
        int xx = w;
#pragma unroll
        for (int o = 1; o < 32; o <<= 1) {
            int y = __shfl_up_sync(0xffffffffu, xx, o);
            if (lane >= o) xx += y;
        }
        wsum[lane] = xx - w;
    }
    __syncthreads();
    int excl = x - v + wsum[wid];
    if (i < Nn) g_rowptr[i] = excl;
    if (tid == 1023) g_bsum[blockIdx.x] = excl + v;
}

__global__ void scan_c_kernel(int nb) {
    __shared__ int ws[4];
    __shared__ int soff;
    int tid = threadIdx.x;
    if (tid < 128) {
        int v = (tid < nb && tid < blockIdx.x) ? g_bsum[tid] : 0;
#pragma unroll
        for (int o = 16; o > 0; o >>= 1) v += __shfl_down_sync(0xffffffffu, v, o);
        if ((tid & 31) == 0) ws[tid >> 5] = v;
    }
    __syncthreads();
    if (tid == 0) soff = ws[0] + ws[1] + ws[2] + ws[3];
    __syncthreads();
    int i = blockIdx.x * 1024 + tid;
    if (i < Nn) {
        int r = g_rowptr[i] + soff;
        g_rowptr[i] = r;
        g_fill[i] = r;
    }
}

__global__ void csr_scatter_kernel(const int* __restrict__ ei) {
    int e = blockIdx.x * blockDim.x + threadIdx.x;
    if (e >= Ee) return;
    int src = __ldg(&ei[e]);
    int dst = __ldg(&ei[Ee + e]);
    int pos = atomicAdd(&g_fill[dst], 1);
    g_csr[pos] = src;
}

// ---------------- x -> fp16 conversion (+ zero g_deg, folded) ----------------
__global__ void convert_x_kernel(const float4* __restrict__ x4, uint2* __restrict__ xh) {
    int i = blockIdx.x * blockDim.x + threadIdx.x;   // Nn*32 float4s
    if (i < Nn) g_deg[i] = 0;
    if (i >= Nn * 32) return;
    float4 v = __ldg(&x4[i]);
    uint2 o;
    o.x = h2u(__floats2half2_rn(v.x, v.y));
    o.y = h2u(__floats2half2_rn(v.z, v.w));
    xh[i] = o;
}

// ---------------- segmented max (gather, fp16 rows) ----------------
// Layer 1: one warp per node, uint2 per lane (4 fp16 feats; row = 256 B). MLP=16.
__global__ void agg_max128_h(const uint2* __restrict__ xh, uint2* __restrict__ aggh) {
    int t = blockIdx.x * blockDim.x + threadIdx.x;
    int w = t >> 5;
    if (w >= Nn) return;
    int lane = t & 31;
    int start = g_rowptr[w];
    int d = g_deg[w];
    unsigned m0 = H2_NEGINF, m1 = H2_NEGINF;
    int i = 0;
    for (; i + 16 <= d; i += 16) {
        int idx[16];
#pragma unroll
        for (int j = 0; j < 16; j++) idx[j] = g_csr[start + i + j];
        uint2 v[16];
#pragma unroll
        for (int j = 0; j < 16; j++) v[j] = __ldg(&xh[(size_t)idx[j] * 32 + lane]);
#pragma unroll
        for (int j = 0; j < 16; j++) { m0 = umax_h2(m0, v[j].x); m1 = umax_h2(m1, v[j].y); }
    }
    if (i + 8 <= d) {
        int idx[8];
#pragma unroll
        for (int j = 0; j < 8; j++) idx[j] = g_csr[start + i + j];
        uint2 v[8];
#pragma unroll
        for (int j = 0; j < 8; j++) v[j] = __ldg(&xh[(size_t)idx[j] * 32 + lane]);
#pragma unroll
        for (int j = 0; j < 8; j++) { m0 = umax_h2(m0, v[j].x); m1 = umax_h2(m1, v[j].y); }
        i += 8;
    }
    if (i + 4 <= d) {
        int idx[4];
#pragma unroll
        for (int j = 0; j < 4; j++) idx[j] = g_csr[start + i + j];
        uint2 v[4];
#pragma unroll
        for (int j = 0; j < 4; j++) v[j] = __ldg(&xh[(size_t)idx[j] * 32 + lane]);
#pragma unroll
        for (int j = 0; j < 4; j++) { m0 = umax_h2(m0, v[j].x); m1 = umax_h2(m1, v[j].y); }
        i += 4;
    }
    for (; i < d; i++) {
        uint2 v = __ldg(&xh[(size_t)g_csr[start + i] * 32 + lane]);
        m0 = umax_h2(m0, v.x); m1 = umax_h2(m1, v.y);
    }
    if (d == 0) { m0 = 0u; m1 = 0u; }
    uint2 o; o.x = m0; o.y = m1;
    aggh[(size_t)w * 32 + lane] = o;
}

// Layers 2/3: one warp per node, one half2 per lane (64 fp16 feats). MLP=16.
__global__ void agg_max64_h(const __half2* __restrict__ hsrc, __half2* __restrict__ aggh) {
    int t = blockIdx.x * blockDim.x + threadIdx.x;
    int w = t >> 5;
    if (w >= Nn) return;
    int lane = t & 31;
    int start = g_rowptr[w];
    int d = g_deg[w];
    unsigned m = H2_NEGINF;
    int i = 0;
    for (; i + 16 <= d; i += 16) {
        int idx[16];
#pragma unroll
        for (int j = 0; j < 16; j++) idx[j] = g_csr[start + i + j];
        unsigned v[16];
#pragma unroll
        for (int j = 0; j < 16; j++) v[j] = h2u(__ldg(&hsrc[(size_t)idx[j] * 32 + lane]));
#pragma unroll
        for (int j = 0; j < 16; j++) m = umax_h2(m, v[j]);
    }
    if (i + 8 <= d) {
        int idx[8];
#pragma unroll
        for (int j = 0; j < 8; j++) idx[j] = g_csr[start + i + j];
        unsigned v[8];
#pragma unroll
        for (int j = 0; j < 8; j++) v[j] = h2u(__ldg(&hsrc[(size_t)idx[j] * 32 + lane]));
#pragma unroll
        for (int j = 0; j < 8; j++) m = umax_h2(m, v[j]);
        i += 8;
    }
    if (i + 4 <= d) {
        int idx[4];
#pragma unroll
        for (int j = 0; j < 4; j++) idx[j] = g_csr[start + i + j];
        unsigned v[4];
#pragma unroll
        for (int j = 0; j < 4; j++) v[j] = h2u(__ldg(&hsrc[(size_t)idx[j] * 32 + lane]));
#pragma unroll
        for (int j = 0; j < 4; j++) m = umax_h2(m, v[j]);
        i += 4;
    }
    for (; i < d; i++)
        m = umax_h2(m, h2u(__ldg(&hsrc[(size_t)g_csr[start + i] * 32 + lane])));
    if (d == 0) m = 0u;
    aggh[(size_t)w * 32 + lane] = u2h(m);
}

// ---------------- fused SAGE layer GEMM (f32x2, 4 nodes x 4 feats per thread) ----
// R12 configuration: measured local optimum (issue mix / regs / occupancy balance).
template <int K, bool OH>
__global__ void __launch_bounds__(256)
sage_gemm(const __half2* __restrict__ agg_h, const __half2* __restrict__ xin_h,
          const float* __restrict__ Wl, const float* __restrict__ blv,
          const float* __restrict__ Wr, void* __restrict__ out_v) {
    __shared__ float sA[64][68];
    __shared__ float sX[64][68];

    const int tid = threadIdx.x;
    const int tx = tid & 15;
    const int ty = tid >> 4;
    const int node0 = blockIdx.x * 64;

    u64 acc[4][2];
#pragma unroll
    for (int i = 0; i < 4; i++) { acc[i][0] = 0ULL; acc[i][1] = 0ULL; }

    for (int k0 = 0; k0 < K; k0 += 64) {
        __syncthreads();
#pragma unroll
        for (int t = tid; t < 64 * 16; t += 256) {
            int nn = t >> 4;
            int ck = t & 15;
            int node = node0 + nn;
            float4 a = make_float4(0.f, 0.f, 0.f, 0.f);
            float4 xv = a;
            if (node < Nn) {
                size_t off = (size_t)node * (K / 2) + (k0 >> 1) + ck * 2;
                uint2 ra = *(const uint2*)&agg_h[off];
                float2 alo = __half22float2(u2h(ra.x));
                float2 ahi = __half22float2(u2h(ra.y));
                a = make_float4(alo.x, alo.y, ahi.x, ahi.y);
                uint2 rx = *(const uint2*)&xin_h[off];
                float2 xlo = __half22float2(u2h(rx.x));
                float2 xhi = __half22float2(u2h(rx.y));
                xv = make_float4(xlo.x, xlo.y, xhi.x, xhi.y);
            }
            *(float4*)&sA[nn][ck * 4] = a;
            *(float4*)&sX[nn][ck * 4] = xv;
        }
        __syncthreads();

#pragma unroll 8
        for (int kk = 0; kk < 64; kk++) {
            const ulonglong2 wl2 = *(const ulonglong2*)&Wl[(size_t)(k0 + kk) * 64 + tx * 4];
            const ulonglong2 wr2 = *(const ulonglong2*)&Wr[(size_t)(k0 + kk) * 64 + tx * 4];
#pragma unroll
            for (int i = 0; i < 4; i++) {
                float a  = sA[ty * 4 + i][kk];
                float xv = sX[ty * 4 + i][kk];
                u64 a2 = pack2(a, a);
                u64 x2 = pack2(xv, xv);
                fma2(acc[i][0], a2, wl2.x);
                fma2(acc[i][1], a2, wl2.y);
                fma2(acc[i][0], x2, wr2.x);
                fma2(acc[i][1], x2, wr2.y);
            }
        }
    }

    const float4 b4 = *(const float4*)&blv[tx * 4];
#pragma unroll
    for (int i = 0; i < 4; i++) {
        int node = node0 + ty * 4 + i;
        if (node < Nn) {
            float2 lo = unpack2(acc[i][0]);
            float2 hi = unpack2(acc[i][1]);
            float4 o;
            o.x = fmaxf(lo.x + b4.x, 0.f);
            o.y = fmaxf(lo.y + b4.y, 0.f);
            o.z = fmaxf(hi.x + b4.z, 0.f);
            o.w = fmaxf(hi.y + b4.w, 0.f);
            if (OH) {
                __half2* oh = (__half2*)out_v;
                uint2 w2;
                w2.x = h2u(__floats2half2_rn(o.x, o.y));
                w2.y = h2u(__floats2half2_rn(o.z, o.w));
                *(uint2*)&oh[(size_t)node * 32 + tx * 2] = w2;
            } else {
                *(float4*)&((float*)out_v)[(size_t)node * 64 + tx * 4] = o;
            }
        }
    }
}

// ---------------- fused attention pooling: one block per graph ----------------
__global__ void __launch_bounds__(256)
fused_pool_kernel(const float4* __restrict__ clo4, const float* __restrict__ Wc,
                  const float* __restrict__ bc, const int* __restrict__ batch,
                  const float* __restrict__ h3,
                  const float* __restrict__ Wa1, const float* __restrict__ ba1,
                  const float* __restrict__ Wa2, const float* __restrict__ ba2,
                  float* __restrict__ out) {
    const int g = blockIdx.x;
    const int tid = threadIdx.x;
    const int lane = tid & 31, wid = tid >> 5;

    __shared__ int sS, sE;
    __shared__ float red[32];
    __shared__ float s_bcast;
    __shared__ float pooled[64];

    if (tid == 0) {
        int lo = 0, hi = Nn;
        while (lo < hi) { int mid = (lo + hi) >> 1; if (batch[mid] < g) lo = mid + 1; else hi = mid; }
        sS = lo;
        hi = Nn;
        while (lo < hi) { int mid = (lo + hi) >> 1; if (batch[mid] < g + 1) lo = mid + 1; else hi = mid; }
        sE = lo;
    }
    __syncthreads();
    const int s = sS, e = sE;
    const int count = e - s;

    float wc[16];
#pragma unroll
    for (int q = 0; q < 16; q++) wc[q] = Wc[q];
    float bias = bc[0];

    float lmax = NEG_INF;
    for (int i = s + tid; i < e; i += 256) {
        float cv = bias;
#pragma unroll
        for (int q = 0; q < 4; q++) {
            float4 c4 = __ldg(&clo4[(size_t)i * 4 + q]);
            cv += c4.x * wc[q * 4 + 0] + c4.y * wc[q * 4 + 1] + c4.z * wc[q * 4 + 2] + c4.w * wc[q * 4 + 3];
        }
        g_c[i] = cv;
        lmax = fmaxf(lmax, cv);
    }
#pragma unroll
    for (int o = 16; o > 0; o >>= 1) lmax = fmaxf(lmax, __shfl_xor_sync(0xffffffffu, lmax, o));
    if (lane == 0) red[wid] = lmax;
    __syncthreads();
    if (tid == 0) {
        float m = red[0];
#pragma unroll
        for (int q = 1; q < 8; q++) m = fmaxf(m, red[q]);
        s_bcast = m;
    }
    __syncthreads();
    const float cmax = s_bcast;

    float lsum = 0.f;
    for (int i = s + tid; i < e; i += 256) {
        float ev = expf(g_c[i] - cmax);
        g_e[i] = ev;
        lsum += ev;
    }
#pragma unroll
    for (int o = 16; o > 0; o >>= 1) lsum += __shfl_xor_sync(0xffffffffu, lsum, o);
    if (lane == 0) red[wid] = lsum;
    __syncthreads();
    if (tid == 0) {
        float m = 0.f;
#pragma unroll
        for (int q = 0; q < 8; q++) m += red[q];
        s_bcast = m;
    }
    __syncthreads();
    const float denom = s_bcast;
    const float scale = (count > 0) ? ((float)count / denom) : 0.f;

    const int f = tid & 63;
    const int grp = tid >> 6;
    float lm = NEG_INF;
    for (int i = s + grp; i < e; i += 4) {
        float p = g_e[i] * scale;
        lm = fmaxf(lm, p * __ldg(&h3[(size_t)i * 64 + f]));
    }
    __syncthreads();
    __shared__ float pgrp[4][64];
    pgrp[grp][f] = lm;
    __syncthreads();
    if (tid < 64) {
        float m = fmaxf(fmaxf(pgrp[0][tid], pgrp[1][tid]), fmaxf(pgrp[2][tid], pgrp[3][tid]));
        pooled[tid] = (count > 0) ? m : 0.f;
    }
    __syncthreads();

    if (tid < 16) {
        float sj = ba1[tid];
        for (int ff = 0; ff < 64; ff++) sj += pooled[ff] * Wa1[ff * 16 + tid];
        sj = fmaxf(sj, 0.f) * Wa2[tid];
#pragma unroll
        for (int o = 8; o > 0; o >>= 1) sj += __shfl_down_sync(0x0000ffffu, sj, o, 16);
        if (tid == 0) out[g] = sj + ba2[0];
    }
}

// ---------------- launch ----------------
extern "C" void kernel_launch(void* const* d_in, const int* in_sizes, int n_in,
                              void* d_out, int out_size) {
    const float* x     = (const float*)d_in[0];
    const int*   ei    = (const int*)d_in[1];
    const int*   batch = (const int*)d_in[2];
    const float* clo   = (const float*)d_in[3];
    const float* W1l = (const float*)d_in[4];
    const float* b1l = (const float*)d_in[5];
    const float* W1r = (const float*)d_in[6];
    const float* W2l = (const float*)d_in[7];
    const float* b2l = (const float*)d_in[8];
    const float* W2r = (const float*)d_in[9];
    const float* W3l = (const float*)d_in[10];
    const float* b3l = (const float*)d_in[11];
    const float* W3r = (const float*)d_in[12];
    const float* Wc  = (const float*)d_in[13];
    const float* bc  = (const float*)d_in[14];
    const float* Wa1 = (const float*)d_in[15];
    const float* ba1 = (const float*)d_in[16];
    const float* Wa2 = (const float*)d_in[17];
    const float* ba2 = (const float*)d_in[18];
    float* out = (float*)d_out;

    __half2* xh;  cudaGetSymbolAddress((void**)&xh, g_xh);
    __half2* agg; cudaGetSymbolAddress((void**)&agg, g_agg);
    __half2* h1;  cudaGetSymbolAddress((void**)&h1, g_h1);
    __half2* h2;  cudaGetSymbolAddress((void**)&h2, g_h2);
    float*   h3;  cudaGetSymbolAddress((void**)&h3, g_h3);

    const int TB = 256;
    const int SCAN_BLOCKS = (Nn + 1023) / 1024;  // 98
    const int GBLK = (Nn + 63) / 64;             // 1563

    // ---- x conversion (also zeroes g_deg) + CSR build (by dst) ----
    convert_x_kernel<<<(Nn * 32 + TB - 1) / TB, TB>>>((const float4*)x, (uint2*)xh);
    hist_kernel<<<(Ee + TB - 1) / TB, TB>>>(ei);
    scan_a_kernel<<<SCAN_BLOCKS, 1024>>>();
    scan_c_kernel<<<SCAN_BLOCKS, 1024>>>(SCAN_BLOCKS);
    csr_scatter_kernel<<<(Ee + TB - 1) / TB, TB>>>(ei);

    // ---- layer 1 (K = 128, fp16 agg+x, fp16 out) ----
    agg_max128_h<<<(Nn * 32 + TB - 1) / TB, TB>>>((const uint2*)xh, (uint2*)agg);
    sage_gemm<128, true><<<GBLK, TB>>>(agg, xh, W1l, b1l, W1r, h1);

    // ---- layer 2 (K = 64, fp16 agg+x, fp16 out) ----
    agg_max64_h<<<(Nn * 32 + TB - 1) / TB, TB>>>(h1, agg);
    sage_gemm<64, true><<<GBLK, TB>>>(agg, h1, W2l, b2l, W2r, h2);

    // ---- layer 3 (K = 64, fp16 agg+x, fp32 out) ----
    agg_max64_h<<<(Nn * 32 + TB - 1) / TB, TB>>>(h2, agg);
    sage_gemm<64, false><<<GBLK, TB>>>(agg, h2, W3l, b3l, W3r, h3);

    // ---- fused attention pooling + readout ----
    fused_pool_kernel<<<GG, 256>>>((const float4*)clo, Wc, bc, batch, h3,
                                   Wa1, ba1, Wa2, ba2, out);
}